// round 9
// baseline (speedup 1.0000x reference)
#include <cuda_runtime.h>
#include <math.h>

#define BSZ 32
#define SEQ 512
#define IDIM 512
#define HDIM 512
#define G4H 2048

#define OUT_HT_ELEMS (BSZ*SEQ*2*HDIM)              // 16777216
#define OUT_HN_OFF   OUT_HT_ELEMS
#define OUT_CN_OFF   (OUT_HT_ELEMS + 2*BSZ*HDIM)   // 16809984
#define OUT_TOTAL    (OUT_CN_OFF + 2*BSZ*HDIM)     // 16842752

// Scratch (allocation-free rule: __device__ globals)
__device__ float    g_G[2][SEQ][BSZ][G4H];   // precomputed x@Wih^T + bias, 256MB
__device__ float    g_h[2][2][BSZ][HDIM];    // [buf][dir][b][k] double-buffered h
__device__ unsigned g_cnt[2][2];             // [dir][grp] arrival counters
__device__ unsigned g_gen[2][2];             // [dir][grp] monotonic generation

__device__ __forceinline__ unsigned ld_acq(const unsigned* p) {
    unsigned v;
    asm volatile("ld.acquire.gpu.global.u32 %0, [%1];" : "=r"(v) : "l"(p));
    return v;
}
__device__ __forceinline__ unsigned atom_add_rel(unsigned* p, unsigned v) {
    unsigned old;
    asm volatile("atom.release.gpu.global.add.u32 %0, [%1], %2;"
                 : "=r"(old) : "l"(p), "r"(v));
    return old;
}
__device__ __forceinline__ void st_rel(unsigned* p, unsigned v) {
    asm volatile("st.release.gpu.global.u32 [%0], %1;" :: "l"(p), "r"(v));
}
__device__ __forceinline__ void fma2(unsigned long long& acc,
                                     unsigned long long a, unsigned long long b) {
    asm("fma.rn.f32x2 %0, %1, %2, %0;" : "+l"(acc) : "l"(a), "l"(b));
}
__device__ __forceinline__ float red2(unsigned long long v) {
    float lo, hi;
    asm("mov.b64 {%0, %1}, %2;" : "=f"(lo), "=f"(hi) : "l"(v));
    return lo + hi;
}
__device__ __forceinline__ unsigned long long dup2(float x) {
    unsigned long long r;
    asm("mov.b64 %0, {%1, %1};" : "=l"(r) : "f"(x));
    return r;
}
__device__ __forceinline__ float2 upk2(unsigned long long v) {
    float2 r;
    asm("mov.b64 {%0, %1}, %2;" : "=f"(r.x), "=f"(r.y) : "l"(v));
    return r;
}
__device__ __forceinline__ float sigm(float x) { return 1.0f / (1.0f + expf(-x)); }

// ---------------------------------------------------------------------------
// Kernel 1: input-projection GEMM, v2: 128x128 tile, 8x8 microtile, f32x2.
// C[m][n] = sum_k X[m][k]*Wih[n][k] + bias[n];  m = b*SEQ + t.
// 256 threads; per k-tile(16): per-thread 3 LDS.128 + 32 FFMA2 per kk
// -> 64B smem per 64 FMA (LDS/FMA balanced at 1B/FMA).
// ---------------------------------------------------------------------------
__global__ void __launch_bounds__(256) ih_gemm_kernel(
    const float* __restrict__ X,
    const float* __restrict__ Wih_f, const float* __restrict__ bih_f, const float* __restrict__ bhh_f,
    const float* __restrict__ Wih_b, const float* __restrict__ bih_b, const float* __restrict__ bhh_b)
{
    __shared__ float Xs[16][132];
    __shared__ float Ws[16][132];

    const int dir = blockIdx.z;
    const float* __restrict__ W   = dir ? Wih_b : Wih_f;
    const float* __restrict__ bih = dir ? bih_b : bih_f;
    const float* __restrict__ bhh = dir ? bhh_b : bhh_f;

    const int tid = threadIdx.x;
    const int tx = tid & 15;          // n micro: 16 x 8 = 128
    const int ty = tid >> 4;          // m micro: 16 x 8 = 128
    const int n0 = blockIdx.x * 128;
    const int m0 = blockIdx.y * 128;
    const int lrow = tid >> 1;        // 0..127
    const int lk   = (tid & 1) * 8;   // 0 or 8

    unsigned long long acc2[8][4];
    #pragma unroll
    for (int i = 0; i < 8; i++)
        #pragma unroll
        for (int j = 0; j < 4; j++) acc2[i][j] = 0ull;

    const float* Xp = X + (size_t)(m0 + lrow) * IDIM + lk;
    const float* Wp = W + (size_t)(n0 + lrow) * IDIM + lk;

    for (int k0 = 0; k0 < IDIM; k0 += 16) {
        float4 x0 = *(const float4*)(Xp + k0);
        float4 x1 = *(const float4*)(Xp + k0 + 4);
        float4 w0 = *(const float4*)(Wp + k0);
        float4 w1 = *(const float4*)(Wp + k0 + 4);
        Xs[lk + 0][lrow] = x0.x; Xs[lk + 1][lrow] = x0.y;
        Xs[lk + 2][lrow] = x0.z; Xs[lk + 3][lrow] = x0.w;
        Xs[lk + 4][lrow] = x1.x; Xs[lk + 5][lrow] = x1.y;
        Xs[lk + 6][lrow] = x1.z; Xs[lk + 7][lrow] = x1.w;
        Ws[lk + 0][lrow] = w0.x; Ws[lk + 1][lrow] = w0.y;
        Ws[lk + 2][lrow] = w0.z; Ws[lk + 3][lrow] = w0.w;
        Ws[lk + 4][lrow] = w1.x; Ws[lk + 5][lrow] = w1.y;
        Ws[lk + 6][lrow] = w1.z; Ws[lk + 7][lrow] = w1.w;
        __syncthreads();
        #pragma unroll
        for (int kk = 0; kk < 16; kk++) {
            float4 a0 = *(const float4*)&Xs[kk][ty * 8];
            float4 a1 = *(const float4*)&Xs[kk][ty * 8 + 4];
            ulonglong2 bq0 = *(const ulonglong2*)&Ws[kk][tx * 8];
            ulonglong2 bq1 = *(const ulonglong2*)&Ws[kk][tx * 8 + 4];
            unsigned long long d[8];
            d[0] = dup2(a0.x); d[1] = dup2(a0.y); d[2] = dup2(a0.z); d[3] = dup2(a0.w);
            d[4] = dup2(a1.x); d[5] = dup2(a1.y); d[6] = dup2(a1.z); d[7] = dup2(a1.w);
            #pragma unroll
            for (int mi = 0; mi < 8; mi++) {
                fma2(acc2[mi][0], d[mi], bq0.x);
                fma2(acc2[mi][1], d[mi], bq0.y);
                fma2(acc2[mi][2], d[mi], bq1.x);
                fma2(acc2[mi][3], d[mi], bq1.y);
            }
        }
        __syncthreads();
    }

    const int n = n0 + tx * 8;
    float bias[8];
    #pragma unroll
    for (int i = 0; i < 8; i++) bias[i] = bih[n + i] + bhh[n + i];

    float* Gout = &g_G[dir][0][0][0];
    #pragma unroll
    for (int mi = 0; mi < 8; mi++) {
        int m = m0 + ty * 8 + mi;
        int b = m >> 9;
        int t = m & 511;
        float2 u0 = upk2(acc2[mi][0]);
        float2 u1 = upk2(acc2[mi][1]);
        float2 u2 = upk2(acc2[mi][2]);
        float2 u3 = upk2(acc2[mi][3]);
        float4 o0, o1;
        o0.x = u0.x + bias[0]; o0.y = u0.y + bias[1];
        o0.z = u1.x + bias[2]; o0.w = u1.y + bias[3];
        o1.x = u2.x + bias[4]; o1.y = u2.y + bias[5];
        o1.z = u3.x + bias[6]; o1.w = u3.y + bias[7];
        float* dst = Gout + ((size_t)(t * BSZ + b) << 11) + n;
        *(float4*)dst = o0;
        *(float4*)(dst + 4) = o1;
    }
}

// ---------------------------------------------------------------------------
// Kernel 2: persistent recurrence, v6 — phase-alternating batch groups.
// 128 CTAs x 512 threads. CTA c: dir=c>>6, owns 8 hidden units (32 gate rows).
// Batch groups A=b0-15, B=b16-31, each with its own grid barrier. ALL threads
// process phase A(s) then B(s): the wait for A(s) targets publishes from
// before the other group's previous phase -> one full phase of straggler
// slack, so waits are normally pre-satisfied (R5 structure, R6 primitives:
// no threadfence/CCTL, ld.acquire poll by warp 0 only, atom.release arrive,
// __ldcg/__stcg for L2-coherent h traffic).
// ---------------------------------------------------------------------------
__global__ void __launch_bounds__(512) rec_kernel(
    const float* __restrict__ Whh_f, const float* __restrict__ Whh_b,
    float* __restrict__ out, int out_size)
{
    __shared__ float hs[16 * HDIM];      // 32KB: current group's h
    __shared__ float gsm[2][32][17];     // [grp][row][b16] gate pre-activations
    __shared__ float csm[8][36];         // [jj][b32] cell state (padded)
    __shared__ unsigned sbase[2];        // per-group gen snapshot

    const int tid  = threadIdx.x;
    const int cta  = blockIdx.x;
    const int dir  = cta >> 6;
    const int cd   = cta & 63;
    const int j0   = cd * 8;
    const int lane = tid & 31;
    const int warp = tid >> 5;           // 0..15
    const int rq   = warp & 7;           // rows 4rq..4rq+3
    const int bh   = warp >> 3;          // group-local b-half: 0..7 / 8..15
    const int q    = (lane >> 1) & 3;
    const int kbase = lane * 16;

    const float* __restrict__ Whh = dir ? Whh_b : Whh_f;

    int off[4];
    #pragma unroll
    for (int j = 0; j < 4; j++) off[j] = (j + q) & 3;

    // snapshot generations BEFORE any arrival (quiescent between replays;
    // gen only advances after all 64 CTAs arrive, which follows all snapshots)
    if (tid == 0) {
        sbase[0] = *(volatile unsigned*)&g_gen[dir][0];
        sbase[1] = *(volatile unsigned*)&g_gen[dir][1];
    }

    // Load 4 rows x 16 k of Whh into packed u64 registers, swizzled k order
    unsigned long long w2[4][8];
    #pragma unroll
    for (int r = 0; r < 4; r++) {
        int r_local = 4 * rq + r;
        int gate = r_local >> 3;
        int jj   = r_local & 7;
        const ulonglong2* wrow =
            (const ulonglong2*)(Whh + (size_t)(gate * HDIM + j0 + jj) * HDIM + kbase);
        #pragma unroll
        for (int j = 0; j < 4; j++) {
            ulonglong2 wv = wrow[off[j]];
            w2[r][2 * j]     = wv.x;
            w2[r][2 * j + 1] = wv.y;
        }
    }

    // zero this direction's initial h (buf 0) + cell state
    if (tid < 256) __stcg(&(&g_h[0][dir][0][0])[cd * 256 + tid], 0.0f);
    for (int i = tid; i < 8 * 36; i += 512) ((float*)csm)[i] = 0.0f;

    // preload step-0 input projections for both groups
    if (tid < 256) {
        const int t0 = dir ? (SEQ - 1) : 0;
        int grp = tid >> 7;
        int lt  = tid & 127;
        int bb = lt >> 3;                 // 0..15 group-local
        int r0 = (lt & 7) * 4;
        int gg = r0 >> 3;
        int j4 = r0 & 7;
        float4 gv = *(const float4*)&g_G[dir][t0][grp * 16 + bb][gg * HDIM + j0 + j4];
        gsm[grp][r0 + 0][bb] = gv.x; gsm[grp][r0 + 1][bb] = gv.y;
        gsm[grp][r0 + 2][bb] = gv.z; gsm[grp][r0 + 3][bb] = gv.w;
    }

    __syncthreads();   // orders zero-init, csm, gsm, sbase
    const unsigned base0 = sbase[0];
    const unsigned base1 = sbase[1];

    // init arrival: publish zeroed h(0) for both groups
    if (tid == 0) {
        #pragma unroll
        for (int grp = 0; grp < 2; grp++) {
            unsigned gbase = grp ? base1 : base0;
            if (atom_add_rel(&g_cnt[dir][grp], 1u) == 63u) {
                g_cnt[dir][grp] = 0u;
                st_rel(&g_gen[dir][grp], gbase + 1u);
            }
        }
    }

    const bool write_tail = (out_size >= OUT_TOTAL);
    const int  r_red  = 4 * rq + ((lane >> 4) & 1) * 2 + ((lane >> 3) & 1);
    const bool writer = ((lane & 7) == 0);
    const bool hi16 = (lane & 16) != 0;
    const bool hi8  = (lane & 8)  != 0;

    for (int s = 0; s < SEQ; s++) {
        const int cur = s & 1, nxt = cur ^ 1;
        const int t = dir ? (SEQ - 1 - s) : s;

        #pragma unroll
        for (int grp = 0; grp < 2; grp++) {
            const unsigned base = grp ? base1 : base0;

            // ---- wait (warp 0 only; normally pre-satisfied) ----
            if (warp == 0) {
                const unsigned target = base + 1u + (unsigned)s;
                while ((int)(ld_acq(&g_gen[dir][grp]) - target) < 0) { }
            }
            __syncthreads();   // A: gen reached; prev phase done with hs

            // ---- stage this group's h[16][512] into smem (L2-coherent) ----
            {
                const float4* src = (const float4*)&g_h[cur][dir][grp * 16][0];
                float4* dst = (float4*)hs;
                #pragma unroll
                for (int i = 0; i < 4; i++)
                    dst[tid + 512 * i] = __ldcg(&src[tid + 512 * i]);
            }
            __syncthreads();   // B: hs ready

            // ---- recurrent GEMM: 8 group-local batch rows per thread ----
            const float* hrow = hs + kbase + bh * (8 * HDIM);
            #pragma unroll 2
            for (int bl = 0; bl < 8; bl++) {
                const int gb = bh * 8 + bl;           // group-local b 0..15
                const ulonglong2* hp = (const ulonglong2*)(hrow + bl * HDIM);
                unsigned long long ha[8];
                #pragma unroll
                for (int j = 0; j < 4; j++) {
                    ulonglong2 hv = hp[off[j]];       // swizzled: conflict-free
                    ha[2 * j]     = hv.x;
                    ha[2 * j + 1] = hv.y;
                }
                unsigned long long a0 = 0, a1 = 0, a2 = 0, a3 = 0;
                #pragma unroll
                for (int j = 0; j < 8; j++) {
                    fma2(a0, ha[j], w2[0][j]);
                    fma2(a1, ha[j], w2[1][j]);
                    fma2(a2, ha[j], w2[2][j]);
                    fma2(a3, ha[j], w2[3][j]);
                }
                float s0 = red2(a0), s1 = red2(a1), s2 = red2(a2), s3 = red2(a3);
                float t0 = hi16 ? s0 : s2;
                float p0 = (hi16 ? s2 : s0) + __shfl_xor_sync(0xffffffffu, t0, 16);
                float t1 = hi16 ? s1 : s3;
                float p1 = (hi16 ? s3 : s1) + __shfl_xor_sync(0xffffffffu, t1, 16);
                float t2 = hi8 ? p0 : p1;
                float v  = (hi8 ? p1 : p0) + __shfl_xor_sync(0xffffffffu, t2, 8);
                v += __shfl_xor_sync(0xffffffffu, v, 4);
                v += __shfl_xor_sync(0xffffffffu, v, 2);
                v += __shfl_xor_sync(0xffffffffu, v, 1);
                if (writer) gsm[grp][r_red][gb] += v;
            }
            __syncthreads();   // C: gsm ready, hs free

            // ---- gates: thread -> (ej, group-local eb) ----
            if (tid < 128) {
                const int ej = tid & 7;
                const int eb = tid >> 3;          // 0..15
                const int b  = grp * 16 + eb;
                float ig = gsm[grp][ej][eb];
                float fg = gsm[grp][8 + ej][eb];
                float gg = gsm[grp][16 + ej][eb];
                float og = gsm[grp][24 + ej][eb];
                float c = csm[ej][b];
                c = sigm(fg) * c + sigm(ig) * tanhf(gg);
                float h = sigm(og) * tanhf(c);
                csm[ej][b] = c;
                __stcg(&g_h[nxt][dir][b][j0 + ej], h);
                out[(size_t)(b * SEQ + t) * (2 * HDIM) + dir * HDIM + j0 + ej] = h;
                if (s == SEQ - 1 && write_tail) {
                    out[OUT_HN_OFF + dir * (BSZ * HDIM) + b * HDIM + j0 + ej] = h;
                    out[OUT_CN_OFF + dir * (BSZ * HDIM) + b * HDIM + j0 + ej] = c;
                }
            }
            __syncthreads();   // D: h stores complete CTA-wide; gsm reads done

            // ---- arrive: publish h(s+1) for this group ----
            if (tid == 0) {
                if (atom_add_rel(&g_cnt[dir][grp], 1u) == 63u) {
                    g_cnt[dir][grp] = 0u;
                    st_rel(&g_gen[dir][grp], base + 2u + (unsigned)s);
                }
            }

            // ---- preload next step's G for this group (gsm[grp] untouched
            //      until the next same-group phase; += there reads it) ----
            if (s + 1 < SEQ && tid < 128) {
                int tn = dir ? (SEQ - 2 - s) : (s + 1);
                int bb = tid >> 3;
                int r0 = (tid & 7) * 4;
                int gg = r0 >> 3;
                int j4 = r0 & 7;
                float4 gv = *(const float4*)&g_G[dir][tn][grp * 16 + bb][gg * HDIM + j0 + j4];
                gsm[grp][r0 + 0][bb] = gv.x; gsm[grp][r0 + 1][bb] = gv.y;
                gsm[grp][r0 + 2][bb] = gv.z; gsm[grp][r0 + 3][bb] = gv.w;
            }
        }
    }
}

extern "C" void kernel_launch(void* const* d_in, const int* in_sizes, int n_in,
                              void* d_out, int out_size) {
    const float* X     = (const float*)d_in[0];
    const float* Wih_f = (const float*)d_in[1];
    const float* Whh_f = (const float*)d_in[2];
    const float* bih_f = (const float*)d_in[3];
    const float* bhh_f = (const float*)d_in[4];
    const float* Wih_b = (const float*)d_in[5];
    const float* Whh_b = (const float*)d_in[6];
    const float* bih_b = (const float*)d_in[7];
    const float* bhh_b = (const float*)d_in[8];
    float* out = (float*)d_out;

    dim3 g1(G4H / 128, (BSZ * SEQ) / 128, 2);
    ih_gemm_kernel<<<g1, 256>>>(X, Wih_f, bih_f, bhh_f, Wih_b, bih_b, bhh_b);
    rec_kernel<<<128, 512>>>(Whh_f, Whh_b, out, out_size);
}

// round 12
// speedup vs baseline: 1.7325x; 1.7325x over previous
#include <cuda_runtime.h>
#include <math.h>

#define BSZ 32
#define SEQ 512
#define IDIM 512
#define HDIM 512
#define G4H 2048

#define OUT_HT_ELEMS (BSZ*SEQ*2*HDIM)              // 16777216
#define OUT_HN_OFF   OUT_HT_ELEMS
#define OUT_CN_OFF   (OUT_HT_ELEMS + 2*BSZ*HDIM)   // 16809984
#define OUT_TOTAL    (OUT_CN_OFF + 2*BSZ*HDIM)     // 16842752

// Scratch (allocation-free rule: __device__ globals)
__device__ float    g_G[2][SEQ][BSZ][G4H];   // precomputed x@Wih^T + bias, 256MB
__device__ float    g_h[2][2][BSZ][HDIM];    // [buf][dir][b][k] double-buffered h
__device__ unsigned g_cnt[2][2];             // [dir][half] arrival counters
__device__ unsigned g_gen[2][2];             // [dir][half] monotonic generation

__device__ __forceinline__ unsigned ld_acq(const unsigned* p) {
    unsigned v;
    asm volatile("ld.acquire.gpu.global.u32 %0, [%1];" : "=r"(v) : "l"(p));
    return v;
}
__device__ __forceinline__ unsigned atom_add_rel(unsigned* p, unsigned v) {
    unsigned old;
    asm volatile("atom.release.gpu.global.add.u32 %0, [%1], %2;"
                 : "=r"(old) : "l"(p), "r"(v));
    return old;
}
__device__ __forceinline__ void st_rel(unsigned* p, unsigned v) {
    asm volatile("st.release.gpu.global.u32 [%0], %1;" :: "l"(p), "r"(v));
}
__device__ __forceinline__ void half_bar(int id) {
    asm volatile("bar.sync %0, 256;" :: "r"(id));
}
__device__ __forceinline__ void fma2(unsigned long long& acc,
                                     unsigned long long a, unsigned long long b) {
    asm("fma.rn.f32x2 %0, %1, %2, %0;" : "+l"(acc) : "l"(a), "l"(b));
}
__device__ __forceinline__ float red2(unsigned long long v) {
    float lo, hi;
    asm("mov.b64 {%0, %1}, %2;" : "=f"(lo), "=f"(hi) : "l"(v));
    return lo + hi;
}
__device__ __forceinline__ unsigned long long dup2(float x) {
    unsigned long long r;
    asm("mov.b64 %0, {%1, %1};" : "=l"(r) : "f"(x));
    return r;
}
__device__ __forceinline__ float2 upk2(unsigned long long v) {
    float2 r;
    asm("mov.b64 {%0, %1}, %2;" : "=f"(r.x), "=f"(r.y) : "l"(v));
    return r;
}
__device__ __forceinline__ float sigm(float x) { return 1.0f / (1.0f + expf(-x)); }

// ---------------------------------------------------------------------------
// Kernel 1: input-projection GEMM (R4 version — part of the 5667us best run).
// 64x64 tile, TK=16, 256 threads, 4x4 register tile as f32x2 pairs.
// ---------------------------------------------------------------------------
__global__ void __launch_bounds__(256) ih_gemm_kernel(
    const float* __restrict__ X,
    const float* __restrict__ Wih_f, const float* __restrict__ bih_f, const float* __restrict__ bhh_f,
    const float* __restrict__ Wih_b, const float* __restrict__ bih_b, const float* __restrict__ bhh_b)
{
    __shared__ float Xs[16][68];
    __shared__ float Ws[16][68];

    const int dir = blockIdx.z;
    const float* __restrict__ W   = dir ? Wih_b : Wih_f;
    const float* __restrict__ bih = dir ? bih_b : bih_f;
    const float* __restrict__ bhh = dir ? bhh_b : bhh_f;

    const int tid = threadIdx.x;
    const int tx = tid & 15;
    const int ty = tid >> 4;
    const int n0 = blockIdx.x * 64;
    const int m0 = blockIdx.y * 64;
    const int lrow = tid >> 2;
    const int lkq  = (tid & 3) * 4;

    unsigned long long acc2[4][2];
    #pragma unroll
    for (int i = 0; i < 4; i++) { acc2[i][0] = 0ull; acc2[i][1] = 0ull; }

    const float* Xp = X + (size_t)(m0 + lrow) * IDIM + lkq;
    const float* Wp = W + (size_t)(n0 + lrow) * IDIM + lkq;

    for (int k0 = 0; k0 < IDIM; k0 += 16) {
        float4 xv = *(const float4*)(Xp + k0);
        float4 wv = *(const float4*)(Wp + k0);
        Xs[lkq + 0][lrow] = xv.x; Xs[lkq + 1][lrow] = xv.y;
        Xs[lkq + 2][lrow] = xv.z; Xs[lkq + 3][lrow] = xv.w;
        Ws[lkq + 0][lrow] = wv.x; Ws[lkq + 1][lrow] = wv.y;
        Ws[lkq + 2][lrow] = wv.z; Ws[lkq + 3][lrow] = wv.w;
        __syncthreads();
        #pragma unroll
        for (int kk = 0; kk < 16; kk++) {
            float4 av = *(const float4*)&Xs[kk][ty * 4];
            ulonglong2 bp = *(const ulonglong2*)&Ws[kk][tx * 4];
            unsigned long long d0 = dup2(av.x);
            unsigned long long d1 = dup2(av.y);
            unsigned long long d2 = dup2(av.z);
            unsigned long long d3 = dup2(av.w);
            fma2(acc2[0][0], d0, bp.x); fma2(acc2[0][1], d0, bp.y);
            fma2(acc2[1][0], d1, bp.x); fma2(acc2[1][1], d1, bp.y);
            fma2(acc2[2][0], d2, bp.x); fma2(acc2[2][1], d2, bp.y);
            fma2(acc2[3][0], d3, bp.x); fma2(acc2[3][1], d3, bp.y);
        }
        __syncthreads();
    }

    const int n = n0 + tx * 4;
    float4 bias4;
    bias4.x = bih[n + 0] + bhh[n + 0];
    bias4.y = bih[n + 1] + bhh[n + 1];
    bias4.z = bih[n + 2] + bhh[n + 2];
    bias4.w = bih[n + 3] + bhh[n + 3];

    float* Gout = &g_G[dir][0][0][0];
    #pragma unroll
    for (int mi = 0; mi < 4; mi++) {
        int m = m0 + ty * 4 + mi;
        int b = m >> 9;
        int t = m & 511;
        float2 u0 = upk2(acc2[mi][0]);
        float2 u1 = upk2(acc2[mi][1]);
        float4 o;
        o.x = u0.x + bias4.x;
        o.y = u0.y + bias4.y;
        o.z = u1.x + bias4.z;
        o.w = u1.y + bias4.w;
        *(float4*)(Gout + ((size_t)(t * BSZ + b) << 11) + n) = o;
    }
}

// ---------------------------------------------------------------------------
// Kernel 2: persistent recurrence, v7 — R6 concurrent halves + two fixes:
//  (1) single poll warp per half + named bar (8x less poll traffic on the
//      gen line the releaser must write);
//  (2) forced anti-phase: half B additionally requires half A to be one step
//      ahead (capped; A never waits on B -> no deadlock), so A's barrier
//      propagation is hidden under B's compute and vice versa.
// 128 CTAs x 512 threads; warps 0-7 <-> b0-15, warps 8-15 <-> b16-31.
// Fence-free sync (ld.acquire / atom.release), __ldcg/__stcg h traffic.
// ---------------------------------------------------------------------------
__global__ void __launch_bounds__(512) rec_kernel(
    const float* __restrict__ Whh_f, const float* __restrict__ Whh_b,
    float* __restrict__ out, int out_size)
{
    __shared__ float hs[32 * HDIM];      // 64KB static: both halves' h
    __shared__ float gsm[32][33];        // [row][b] gate pre-activations
    __shared__ float csm[8][36];         // [jj][b] cell state (padded)
    __shared__ unsigned sbase[2];        // per-half gen snapshot

    const int tid  = threadIdx.x;
    const int cta  = blockIdx.x;
    const int dir  = cta >> 6;
    const int cd   = cta & 63;
    const int j0   = cd * 8;
    const int lane = tid & 31;
    const int warp = tid >> 5;           // 0..15
    const int rq   = warp & 7;           // rows 4rq..4rq+3
    const int bh   = warp >> 3;          // batch half (pipeline id)
    const int lt   = tid & 255;          // thread id within half
    const int barid = 1 + bh;
    const int q    = (lane >> 1) & 3;
    const int kbase = lane * 16;

    const float* __restrict__ Whh = dir ? Whh_b : Whh_f;

    int off[4];
    #pragma unroll
    for (int j = 0; j < 4; j++) off[j] = (j + q) & 3;

    // snapshot generations BEFORE any arrival (quiescent between replays)
    if (tid == 0) {
        sbase[0] = *(volatile unsigned*)&g_gen[dir][0];
        sbase[1] = *(volatile unsigned*)&g_gen[dir][1];
    }

    // Load 4 rows x 16 k of Whh into packed u64 registers, swizzled k order
    unsigned long long w2[4][8];
    #pragma unroll
    for (int r = 0; r < 4; r++) {
        int r_local = 4 * rq + r;
        int gate = r_local >> 3;
        int jj   = r_local & 7;
        const ulonglong2* wrow =
            (const ulonglong2*)(Whh + (size_t)(gate * HDIM + j0 + jj) * HDIM + kbase);
        #pragma unroll
        for (int j = 0; j < 4; j++) {
            ulonglong2 wv = wrow[off[j]];
            w2[r][2 * j]     = wv.x;
            w2[r][2 * j + 1] = wv.y;
        }
    }

    // zero this direction's initial h (buf 0) + cell state
    if (tid < 256) __stcg(&(&g_h[0][dir][0][0])[cd * 256 + tid], 0.0f);
    for (int i = tid; i < 8 * 36; i += 512) ((float*)csm)[i] = 0.0f;

    // preload step-0 input projection for this half
    if (lt < 128) {
        const int t0 = dir ? (SEQ - 1) : 0;
        int bb = bh * 16 + (lt >> 3);
        int r0 = (lt & 7) * 4;
        int gg = r0 >> 3;
        int j4 = r0 & 7;
        float4 gv = *(const float4*)&g_G[dir][t0][bb][gg * HDIM + j0 + j4];
        gsm[r0 + 0][bb] = gv.x; gsm[r0 + 1][bb] = gv.y;
        gsm[r0 + 2][bb] = gv.z; gsm[r0 + 3][bb] = gv.w;
    }

    __syncthreads();   // orders zero-init, csm, gsm, sbase for everyone
    const unsigned base0 = sbase[0];
    const unsigned base1 = sbase[1];
    const unsigned base  = bh ? base1 : base0;

    // init arrival: publish zeroed h(0) for this half
    if (lt == 0) {
        if (atom_add_rel(&g_cnt[dir][bh], 1u) == 63u) {
            g_cnt[dir][bh] = 0u;
            st_rel(&g_gen[dir][bh], base + 1u);
        }
    }

    const bool write_tail = (out_size >= OUT_TOTAL);
    const int  r_red  = 4 * rq + ((lane >> 4) & 1) * 2 + ((lane >> 3) & 1);
    const bool writer = ((lane & 7) == 0);
    const bool hi16 = (lane & 16) != 0;
    const bool hi8  = (lane & 8)  != 0;
    const bool pollwarp = (warp == bh * 8);   // warp 0 / warp 8

    for (int s = 0; s < SEQ; s++) {
        const int cur = s & 1, nxt = cur ^ 1;
        const int t = dir ? (SEQ - 1 - s) : s;

        // ---- wait: h(s) for this half (single poll warp, then named bar) ----
        if (pollwarp) {
            const unsigned target = base + 1u + (unsigned)s;
            while ((int)(ld_acq(&g_gen[dir][bh]) - target) < 0) { }
            if (bh == 1) {
                // anti-phase skew: require half A to have FINISHED step
                // min(s+1, SEQ-1) (gen_A = base0 + 2 + k after step k).
                const int k = (s + 1 < SEQ) ? (s + 1) : (SEQ - 1);
                const unsigned ta = base0 + 2u + (unsigned)k;
                while ((int)(ld_acq(&g_gen[dir][0]) - ta) < 0) { }
            }
        }
        half_bar(barid);

        // ---- stage this half's h[16][512] into smem (L1-bypassing loads) ----
        {
            const float4* src = (const float4*)&g_h[cur][dir][bh * 16][0];
            float4* dst = (float4*)(hs + bh * 16 * HDIM);
            #pragma unroll
            for (int i = 0; i < 8; i++)
                dst[lt + 256 * i] = __ldcg(&src[lt + 256 * i]);
        }
        half_bar(barid);

        // ---- recurrent GEMM for this half's 16 batch rows ----
        const float* hrow = hs + kbase + bh * (16 * HDIM);
        #pragma unroll 2
        for (int bl = 0; bl < 16; bl++) {
            const int b = bh * 16 + bl;
            const ulonglong2* hp = (const ulonglong2*)(hrow + bl * HDIM);
            unsigned long long ha[8];
            #pragma unroll
            for (int j = 0; j < 4; j++) {
                ulonglong2 hv = hp[off[j]];       // swizzled: conflict-free
                ha[2 * j]     = hv.x;
                ha[2 * j + 1] = hv.y;
            }
            unsigned long long a0 = 0, a1 = 0, a2 = 0, a3 = 0;
            #pragma unroll
            for (int j = 0; j < 8; j++) {
                fma2(a0, ha[j], w2[0][j]);
                fma2(a1, ha[j], w2[1][j]);
                fma2(a2, ha[j], w2[2][j]);
                fma2(a3, ha[j], w2[3][j]);
            }
            float s0 = red2(a0), s1 = red2(a1), s2 = red2(a2), s3 = red2(a3);
            float t0 = hi16 ? s0 : s2;
            float p0 = (hi16 ? s2 : s0) + __shfl_xor_sync(0xffffffffu, t0, 16);
            float t1 = hi16 ? s1 : s3;
            float p1 = (hi16 ? s3 : s1) + __shfl_xor_sync(0xffffffffu, t1, 16);
            float t2 = hi8 ? p0 : p1;
            float v  = (hi8 ? p1 : p0) + __shfl_xor_sync(0xffffffffu, t2, 8);
            v += __shfl_xor_sync(0xffffffffu, v, 4);
            v += __shfl_xor_sync(0xffffffffu, v, 2);
            v += __shfl_xor_sync(0xffffffffu, v, 1);
            if (writer) gsm[r_red][b] += v;       // one writer per (row,b)
        }
        half_bar(barid);

        // ---- gates for this half: thread -> (ej, b) ----
        if (lt < 128) {
            const int ej = lt & 7;
            const int b  = bh * 16 + (lt >> 3);
            float ig = gsm[ej][b];
            float fg = gsm[8 + ej][b];
            float gg = gsm[16 + ej][b];
            float og = gsm[24 + ej][b];
            float c = csm[ej][b];
            c = sigm(fg) * c + sigm(ig) * tanhf(gg);
            float h = sigm(og) * tanhf(c);
            csm[ej][b] = c;
            __stcg(&g_h[nxt][dir][b][j0 + ej], h);
            out[(size_t)(b * SEQ + t) * (2 * HDIM) + dir * HDIM + j0 + ej] = h;
            if (s == SEQ - 1 && write_tail) {
                out[OUT_HN_OFF + dir * (BSZ * HDIM) + b * HDIM + j0 + ej] = h;
                out[OUT_CN_OFF + dir * (BSZ * HDIM) + b * HDIM + j0 + ej] = c;
            }
        }
        half_bar(barid);   // h stores + gsm reads done for this half

        // ---- arrive: publish h(s+1) for this half ----
        if (lt == 0) {
            if (atom_add_rel(&g_cnt[dir][bh], 1u) == 63u) {
                g_cnt[dir][bh] = 0u;
                st_rel(&g_gen[dir][bh], base + 2u + (unsigned)s);
            }
        }

        // ---- preload next step's G for this half ----
        if (s + 1 < SEQ && lt < 128) {
            int tn = dir ? (SEQ - 2 - s) : (s + 1);
            int bb = bh * 16 + (lt >> 3);
            int r0 = (lt & 7) * 4;
            int gg = r0 >> 3;
            int j4 = r0 & 7;
            float4 gv = *(const float4*)&g_G[dir][tn][bb][gg * HDIM + j0 + j4];
            gsm[r0 + 0][bb] = gv.x; gsm[r0 + 1][bb] = gv.y;
            gsm[r0 + 2][bb] = gv.z; gsm[r0 + 3][bb] = gv.w;
        }
    }
}

extern "C" void kernel_launch(void* const* d_in, const int* in_sizes, int n_in,
                              void* d_out, int out_size) {
    const float* X     = (const float*)d_in[0];
    const float* Wih_f = (const float*)d_in[1];
    const float* Whh_f = (const float*)d_in[2];
    const float* bih_f = (const float*)d_in[3];
    const float* bhh_f = (const float*)d_in[4];
    const float* Wih_b = (const float*)d_in[5];
    const float* Whh_b = (const float*)d_in[6];
    const float* bih_b = (const float*)d_in[7];
    const float* bhh_b = (const float*)d_in[8];
    float* out = (float*)d_out;

    dim3 g1(G4H / 64, (BSZ * SEQ) / 64, 2);
    ih_gemm_kernel<<<g1, 256>>>(X, Wih_f, bih_f, bhh_f, Wih_b, bih_b, bhh_b);
    rec_kernel<<<128, 512>>>(Whh_f, Whh_b, out, out_size);
}

// round 15
// speedup vs baseline: 1.7795x; 1.0271x over previous
#include <cuda_runtime.h>
#include <math.h>

#define BSZ 32
#define SEQ 512
#define IDIM 512
#define HDIM 512
#define G4H 2048

#define OUT_HT_ELEMS (BSZ*SEQ*2*HDIM)              // 16777216
#define OUT_HN_OFF   OUT_HT_ELEMS
#define OUT_CN_OFF   (OUT_HT_ELEMS + 2*BSZ*HDIM)   // 16809984
#define OUT_TOTAL    (OUT_CN_OFF + 2*BSZ*HDIM)     // 16842752

// Scratch (allocation-free rule: __device__ globals)
__device__ float    g_G[2][SEQ][BSZ][G4H];   // precomputed x@Wih^T + bias, 256MB
__device__ float    g_h[2][2][BSZ][HDIM];    // [buf][dir][b][k] double-buffered h
__device__ unsigned g_flag[2][2][64];        // [dir][half][cta] monotonic step flags

__device__ __forceinline__ unsigned ld_acq(const unsigned* p) {
    unsigned v;
    asm volatile("ld.acquire.gpu.global.u32 %0, [%1];" : "=r"(v) : "l"(p));
    return v;
}
__device__ __forceinline__ void st_rel(unsigned* p, unsigned v) {
    asm volatile("st.release.gpu.global.u32 [%0], %1;" :: "l"(p), "r"(v));
}
__device__ __forceinline__ void half_bar(int id) {
    asm volatile("bar.sync %0, 256;" :: "r"(id));
}
__device__ __forceinline__ void fma2(unsigned long long& acc,
                                     unsigned long long a, unsigned long long b) {
    asm("fma.rn.f32x2 %0, %1, %2, %0;" : "+l"(acc) : "l"(a), "l"(b));
}
__device__ __forceinline__ float red2(unsigned long long v) {
    float lo, hi;
    asm("mov.b64 {%0, %1}, %2;" : "=f"(lo), "=f"(hi) : "l"(v));
    return lo + hi;
}
__device__ __forceinline__ unsigned long long dup2(float x) {
    unsigned long long r;
    asm("mov.b64 %0, {%1, %1};" : "=l"(r) : "f"(x));
    return r;
}
__device__ __forceinline__ float2 upk2(unsigned long long v) {
    float2 r;
    asm("mov.b64 {%0, %1}, %2;" : "=f"(r.x), "=f"(r.y) : "l"(v));
    return r;
}
__device__ __forceinline__ float sigm(float x) {
    return 1.0f / (1.0f + __expf(-x));
}
__device__ __forceinline__ float tanh_fast(float x) {
    float xc = fminf(fmaxf(x, -10.0f), 10.0f);   // tanh(±10)=±1 in fp32; no overflow
    float e = __expf(2.0f * xc);
    return (e - 1.0f) / (e + 1.0f);
}

// ---------------------------------------------------------------------------
// Kernel 1: input-projection GEMM (R4 version — part of the best run).
// 64x64 tile, TK=16, 256 threads, 4x4 register tile as f32x2 pairs.
// ---------------------------------------------------------------------------
__global__ void __launch_bounds__(256) ih_gemm_kernel(
    const float* __restrict__ X,
    const float* __restrict__ Wih_f, const float* __restrict__ bih_f, const float* __restrict__ bhh_f,
    const float* __restrict__ Wih_b, const float* __restrict__ bih_b, const float* __restrict__ bhh_b)
{
    __shared__ float Xs[16][68];
    __shared__ float Ws[16][68];

    const int dir = blockIdx.z;
    const float* __restrict__ W   = dir ? Wih_b : Wih_f;
    const float* __restrict__ bih = dir ? bih_b : bih_f;
    const float* __restrict__ bhh = dir ? bhh_b : bhh_f;

    const int tid = threadIdx.x;
    const int tx = tid & 15;
    const int ty = tid >> 4;
    const int n0 = blockIdx.x * 64;
    const int m0 = blockIdx.y * 64;
    const int lrow = tid >> 2;
    const int lkq  = (tid & 3) * 4;

    unsigned long long acc2[4][2];
    #pragma unroll
    for (int i = 0; i < 4; i++) { acc2[i][0] = 0ull; acc2[i][1] = 0ull; }

    const float* Xp = X + (size_t)(m0 + lrow) * IDIM + lkq;
    const float* Wp = W + (size_t)(n0 + lrow) * IDIM + lkq;

    for (int k0 = 0; k0 < IDIM; k0 += 16) {
        float4 xv = *(const float4*)(Xp + k0);
        float4 wv = *(const float4*)(Wp + k0);
        Xs[lkq + 0][lrow] = xv.x; Xs[lkq + 1][lrow] = xv.y;
        Xs[lkq + 2][lrow] = xv.z; Xs[lkq + 3][lrow] = xv.w;
        Ws[lkq + 0][lrow] = wv.x; Ws[lkq + 1][lrow] = wv.y;
        Ws[lkq + 2][lrow] = wv.z; Ws[lkq + 3][lrow] = wv.w;
        __syncthreads();
        #pragma unroll
        for (int kk = 0; kk < 16; kk++) {
            float4 av = *(const float4*)&Xs[kk][ty * 4];
            ulonglong2 bp = *(const ulonglong2*)&Ws[kk][tx * 4];
            unsigned long long d0 = dup2(av.x);
            unsigned long long d1 = dup2(av.y);
            unsigned long long d2 = dup2(av.z);
            unsigned long long d3 = dup2(av.w);
            fma2(acc2[0][0], d0, bp.x); fma2(acc2[0][1], d0, bp.y);
            fma2(acc2[1][0], d1, bp.x); fma2(acc2[1][1], d1, bp.y);
            fma2(acc2[2][0], d2, bp.x); fma2(acc2[2][1], d2, bp.y);
            fma2(acc2[3][0], d3, bp.x); fma2(acc2[3][1], d3, bp.y);
        }
        __syncthreads();
    }

    const int n = n0 + tx * 4;
    float4 bias4;
    bias4.x = bih[n + 0] + bhh[n + 0];
    bias4.y = bih[n + 1] + bhh[n + 1];
    bias4.z = bih[n + 2] + bhh[n + 2];
    bias4.w = bih[n + 3] + bhh[n + 3];

    float* Gout = &g_G[dir][0][0][0];
    #pragma unroll
    for (int mi = 0; mi < 4; mi++) {
        int m = m0 + ty * 4 + mi;
        int b = m >> 9;
        int t = m & 511;
        float2 u0 = upk2(acc2[mi][0]);
        float2 u1 = upk2(acc2[mi][1]);
        float4 o;
        o.x = u0.x + bias4.x;
        o.y = u0.y + bias4.y;
        o.z = u1.x + bias4.z;
        o.w = u1.y + bias4.w;
        *(float4*)(Gout + ((size_t)(t * BSZ + b) << 11) + n) = o;
    }
}

// ---------------------------------------------------------------------------
// Kernel 2: persistent recurrence, v9 — R12 structure with:
//  (a) proven shfl-fold reduction (redux.f32 doesn't exist on sm_103);
//  (b) fast-math gates (__expf-based; err ~2^-21 vs 1e-3 budget);
//  (c) per-CTA flag barrier: arrival = st.release to OWN word (no 64-way
//      atomic serialization, no counter reset); poll warp checks 64 flags
//      (2 per lane) with ballot. Flags are all-equal between launches.
// 128 CTAs x 512 threads; warps 0-7 <-> b0-15, warps 8-15 <-> b16-31 as two
// concurrent pipelines with named CTA bars. __ldcg/__stcg h traffic.
// ---------------------------------------------------------------------------
__global__ void __launch_bounds__(512) rec_kernel(
    const float* __restrict__ Whh_f, const float* __restrict__ Whh_b,
    float* __restrict__ out, int out_size)
{
    __shared__ float hs[32 * HDIM];      // 64KB static: both halves' h
    __shared__ float gsm[32][33];        // [row][b] gate pre-activations
    __shared__ float csm[8][36];         // [jj][b] cell state (padded)
    __shared__ unsigned sbase[2];        // per-half gen snapshot

    const int tid  = threadIdx.x;
    const int cta  = blockIdx.x;
    const int dir  = cta >> 6;
    const int cd   = cta & 63;
    const int j0   = cd * 8;
    const int lane = tid & 31;
    const int warp = tid >> 5;           // 0..15
    const int rq   = warp & 7;           // rows 4rq..4rq+3
    const int bh   = warp >> 3;          // batch half (pipeline id)
    const int lt   = tid & 255;          // thread id within half
    const int barid = 1 + bh;
    const int q    = (lane >> 1) & 3;
    const int kbase = lane * 16;

    const float* __restrict__ Whh = dir ? Whh_b : Whh_f;

    int off[4];
    #pragma unroll
    for (int j = 0; j < 4; j++) off[j] = (j + q) & 3;

    // snapshot own flag BEFORE any store (all flags equal between replays)
    if (tid == 0) {
        sbase[0] = *(volatile unsigned*)&g_flag[dir][0][cd];
        sbase[1] = *(volatile unsigned*)&g_flag[dir][1][cd];
    }

    // Load 4 rows x 16 k of Whh into packed u64 registers, swizzled k order
    unsigned long long w2[4][8];
    #pragma unroll
    for (int r = 0; r < 4; r++) {
        int r_local = 4 * rq + r;
        int gate = r_local >> 3;
        int jj   = r_local & 7;
        const ulonglong2* wrow =
            (const ulonglong2*)(Whh + (size_t)(gate * HDIM + j0 + jj) * HDIM + kbase);
        #pragma unroll
        for (int j = 0; j < 4; j++) {
            ulonglong2 wv = wrow[off[j]];
            w2[r][2 * j]     = wv.x;
            w2[r][2 * j + 1] = wv.y;
        }
    }

    // zero this direction's initial h (buf 0) + cell state
    if (tid < 256) __stcg(&(&g_h[0][dir][0][0])[cd * 256 + tid], 0.0f);
    for (int i = tid; i < 8 * 36; i += 512) ((float*)csm)[i] = 0.0f;

    // preload step-0 input projection for this half
    if (lt < 128) {
        const int t0 = dir ? (SEQ - 1) : 0;
        int bb = bh * 16 + (lt >> 3);
        int r0 = (lt & 7) * 4;
        int gg = r0 >> 3;
        int j4 = r0 & 7;
        float4 gv = *(const float4*)&g_G[dir][t0][bb][gg * HDIM + j0 + j4];
        gsm[r0 + 0][bb] = gv.x; gsm[r0 + 1][bb] = gv.y;
        gsm[r0 + 2][bb] = gv.z; gsm[r0 + 3][bb] = gv.w;
    }

    __syncthreads();   // orders zero-init, csm, gsm, sbase for everyone
    const unsigned base0 = sbase[0];
    const unsigned base1 = sbase[1];
    const unsigned base  = bh ? base1 : base0;

    // init arrival: publish zeroed h(0) for this half (own flag only)
    if (lt == 0) st_rel(&g_flag[dir][bh][cd], base + 1u);

    const bool write_tail = (out_size >= OUT_TOTAL);
    const int  r_red  = 4 * rq + ((lane >> 4) & 1) * 2 + ((lane >> 3) & 1);
    const bool writer = ((lane & 7) == 0);
    const bool hi16 = (lane & 16) != 0;
    const bool hi8  = (lane & 8)  != 0;
    const bool pollwarp = (warp == bh * 8);   // warp 0 / warp 8

    for (int s = 0; s < SEQ; s++) {
        const int cur = s & 1, nxt = cur ^ 1;
        const int t = dir ? (SEQ - 1 - s) : s;

        // ---- wait: all 64 CTAs published h(s) for this half ----
        if (pollwarp) {
            const unsigned* fl = &g_flag[dir][bh][0];
            const unsigned target = base + 1u + (unsigned)s;
            for (;;) {
                bool ok = ((int)(ld_acq(fl + lane) - target) >= 0) &&
                          ((int)(ld_acq(fl + lane + 32) - target) >= 0);
                if (__all_sync(0xffffffffu, ok)) break;
            }
            if (bh == 1) {
                // anti-phase skew: half A must have FINISHED step min(s+1,511)
                const int k = (s + 1 < SEQ) ? (s + 1) : (SEQ - 1);
                const unsigned ta = base0 + 2u + (unsigned)k;
                const unsigned* fa = &g_flag[dir][0][0];
                for (;;) {
                    bool ok = ((int)(ld_acq(fa + lane) - ta) >= 0) &&
                              ((int)(ld_acq(fa + lane + 32) - ta) >= 0);
                    if (__all_sync(0xffffffffu, ok)) break;
                }
            }
        }
        half_bar(barid);

        // ---- stage this half's h[16][512] into smem (L1-bypassing loads) ----
        {
            const float4* src = (const float4*)&g_h[cur][dir][bh * 16][0];
            float4* dst = (float4*)(hs + bh * 16 * HDIM);
            #pragma unroll
            for (int i = 0; i < 8; i++)
                dst[lt + 256 * i] = __ldcg(&src[lt + 256 * i]);
        }
        half_bar(barid);

        // ---- recurrent GEMM for this half's 16 batch rows ----
        const float* hrow = hs + kbase + bh * (16 * HDIM);
        #pragma unroll 2
        for (int bl = 0; bl < 16; bl++) {
            const int b = bh * 16 + bl;
            const ulonglong2* hp = (const ulonglong2*)(hrow + bl * HDIM);
            unsigned long long ha[8];
            #pragma unroll
            for (int j = 0; j < 4; j++) {
                ulonglong2 hv = hp[off[j]];       // swizzled: conflict-free
                ha[2 * j]     = hv.x;
                ha[2 * j + 1] = hv.y;
            }
            unsigned long long a0 = 0, a1 = 0, a2 = 0, a3 = 0;
            #pragma unroll
            for (int j = 0; j < 8; j++) {
                fma2(a0, ha[j], w2[0][j]);
                fma2(a1, ha[j], w2[1][j]);
                fma2(a2, ha[j], w2[2][j]);
                fma2(a3, ha[j], w2[3][j]);
            }
            float s0 = red2(a0), s1 = red2(a1), s2 = red2(a2), s3 = red2(a3);
            float t0 = hi16 ? s0 : s2;
            float p0 = (hi16 ? s2 : s0) + __shfl_xor_sync(0xffffffffu, t0, 16);
            float t1 = hi16 ? s1 : s3;
            float p1 = (hi16 ? s3 : s1) + __shfl_xor_sync(0xffffffffu, t1, 16);
            float t2 = hi8 ? p0 : p1;
            float v  = (hi8 ? p1 : p0) + __shfl_xor_sync(0xffffffffu, t2, 8);
            v += __shfl_xor_sync(0xffffffffu, v, 4);
            v += __shfl_xor_sync(0xffffffffu, v, 2);
            v += __shfl_xor_sync(0xffffffffu, v, 1);
            if (writer) gsm[r_red][b] += v;       // one writer per (row,b)
        }
        half_bar(barid);

        // ---- gates for this half: thread -> (ej, b) ----
        if (lt < 128) {
            const int ej = lt & 7;
            const int b  = bh * 16 + (lt >> 3);
            float ig = gsm[ej][b];
            float fg = gsm[8 + ej][b];
            float gg = gsm[16 + ej][b];
            float og = gsm[24 + ej][b];
            float c = csm[ej][b];
            c = sigm(fg) * c + sigm(ig) * tanh_fast(gg);
            float h = sigm(og) * tanh_fast(c);
            csm[ej][b] = c;
            __stcg(&g_h[nxt][dir][b][j0 + ej], h);
            out[(size_t)(b * SEQ + t) * (2 * HDIM) + dir * HDIM + j0 + ej] = h;
            if (s == SEQ - 1 && write_tail) {
                out[OUT_HN_OFF + dir * (BSZ * HDIM) + b * HDIM + j0 + ej] = h;
                out[OUT_CN_OFF + dir * (BSZ * HDIM) + b * HDIM + j0 + ej] = c;
            }
        }
        half_bar(barid);   // h stores + gsm reads done for this half

        // ---- arrive: publish h(s+1) — own flag, no atomics ----
        if (lt == 0) st_rel(&g_flag[dir][bh][cd], base + 2u + (unsigned)s);

        // ---- preload next step's G for this half ----
        if (s + 1 < SEQ && lt < 128) {
            int tn = dir ? (SEQ - 2 - s) : (s + 1);
            int bb = bh * 16 + (lt >> 3);
            int r0 = (lt & 7) * 4;
            int gg = r0 >> 3;
            int j4 = r0 & 7;
            float4 gv = *(const float4*)&g_G[dir][tn][bb][gg * HDIM + j0 + j4];
            gsm[r0 + 0][bb] = gv.x; gsm[r0 + 1][bb] = gv.y;
            gsm[r0 + 2][bb] = gv.z; gsm[r0 + 3][bb] = gv.w;
        }
    }
}

extern "C" void kernel_launch(void* const* d_in, const int* in_sizes, int n_in,
                              void* d_out, int out_size) {
    const float* X     = (const float*)d_in[0];
    const float* Wih_f = (const float*)d_in[1];
    const float* Whh_f = (const float*)d_in[2];
    const float* bih_f = (const float*)d_in[3];
    const float* bhh_f = (const float*)d_in[4];
    const float* Wih_b = (const float*)d_in[5];
    const float* Whh_b = (const float*)d_in[6];
    const float* bih_b = (const float*)d_in[7];
    const float* bhh_b = (const float*)d_in[8];
    float* out = (float*)d_out;

    dim3 g1(G4H / 64, (BSZ * SEQ) / 64, 2);
    ih_gemm_kernel<<<g1, 256>>>(X, Wih_f, bih_f, bhh_f, Wih_b, bih_b, bhh_b);
    rec_kernel<<<128, 512>>>(Whh_f, Whh_b, out, out_size);
}